// round 15
// baseline (speedup 1.0000x reference)
#include <cuda_runtime.h>
#include <cuda_fp16.h>
#include <cstdint>
#include <cstddef>

#define DEVI __device__ __forceinline__

// ---------------- problem constants ----------------
constexpr int Bn = 8;
constexpr int Sn = 1024;
constexpr int Dn = 1024;

// ---------------- GEMM tiling ----------------
// BK=32: halves stage smem -> qk 3 CTAs/SM, pv 4 CTAs/SM (occupancy lever)
// (R14 resubmission: infra flake, occupancy experiment unrun)
constexpr int BM = 128, BN = 64, BK = 32;
constexpr int NIT = Dn / BK;            // 32 k-iterations
constexpr int ROWB = 80;                // padded smem row: 32 halves (64B) + 16B pad
constexpr int TILE_A = BM * ROWB;       // 10240 B (128-row tile)
constexpr int TILE_Bt = BN * ROWB;      // 5120 B  (64-row tile)

// GEMM1 (Q K^T): Ah, Al (128-row) + Bh, Bl (64-row)
constexpr int S1_AH = 0, S1_AL = TILE_A, S1_BH = 2 * TILE_A, S1_BL = 2 * TILE_A + TILE_Bt;
constexpr int STAGE1_B = 2 * TILE_A + 2 * TILE_Bt;   // 30720
constexpr int KS_OFF = 2 * STAGE1_B;                 // 61440
constexpr int SMEM1 = KS_OFF + 512;                  // 61952  (3 CTAs/SM)

// GEMM2 (P V): Ph (128-row) + Vh, Vl (64-row)
constexpr int S2_A = 0, S2_BH = TILE_A, S2_BL = TILE_A + TILE_Bt;
constexpr int STAGE2_B = TILE_A + 2 * TILE_Bt;       // 20480
constexpr int SMEM2 = 2 * STAGE2_B;                  // 40960  (4 CTAs/SM)

// ---------------- scratch (device globals; no allocation) ----------------
__device__ __half g_Qh[(size_t)Bn * Sn * Dn], g_Ql[(size_t)Bn * Sn * Dn];
__device__ __half g_Kh[(size_t)Bn * Sn * Dn], g_Kl[(size_t)Bn * Sn * Dn];
__device__ __half g_Vth[(size_t)Bn * Dn * Sn], g_Vtl[(size_t)Bn * Dn * Sn]; // V^T [b][d][t]
__device__ __half g_Ph[(size_t)Bn * Sn * Sn];
__device__ float  g_L[(size_t)Bn * Sn * Sn];
__device__ float  g_ksum[Bn * Sn];
__device__ int    g_stage[Bn];

// ---------------- helpers ----------------
DEVI uint32_t smem_u32(const void* p) {
    uint32_t a;
    asm("{ .reg .u64 t; cvta.to.shared.u64 t, %1; cvt.u32.u64 %0, t; }"
        : "=r"(a) : "l"(p));
    return a;
}
DEVI uint32_t pack2(__half a, __half b) {
    __half2 t = __halves2half2(a, b);
    return *reinterpret_cast<uint32_t*>(&t);
}

#define CP_COMMIT() asm volatile("cp.async.commit_group;")
#define CP_WAIT0()  asm volatile("cp.async.wait_group 0;")

DEVI void cp16(uint32_t dst, const void* src) {
    asm volatile("cp.async.cg.shared.global [%0], [%1], 16;" :: "r"(dst), "l"(src));
}

DEVI void ldsm4(uint32_t* r, uint32_t addr) {
    asm volatile("ldmatrix.sync.aligned.m8n8.x4.shared.b16 {%0,%1,%2,%3}, [%4];"
        : "=r"(r[0]), "=r"(r[1]), "=r"(r[2]), "=r"(r[3]) : "r"(addr));
}

DEVI void mma16816(float* c, const uint32_t* a, const uint32_t* b) {
    asm volatile(
        "mma.sync.aligned.m16n8k16.row.col.f32.f16.f16.f32 "
        "{%0,%1,%2,%3}, {%4,%5,%6,%7}, {%8,%9}, {%0,%1,%2,%3};"
        : "+f"(c[0]), "+f"(c[1]), "+f"(c[2]), "+f"(c[3])
        : "r"(a[0]), "r"(a[1]), "r"(a[2]), "r"(a[3]), "r"(b[0]), "r"(b[1]));
}

// 128-row x 32-half tile global->smem (512 x 16B chunks, 2 per thread)
DEVI void load_tile128(uint32_t dst, const __half* src, int tid) {
#pragma unroll
    for (int j = 0; j < 2; j++) {
        int idx = j * 256 + tid;
        int row = idx >> 2, q = idx & 3;
        cp16(dst + (uint32_t)row * ROWB + q * 16, src + (size_t)row * 1024 + q * 8);
    }
}
// 64-row x 32-half tile global->smem (256 x 16B chunks, 1 per thread)
DEVI void load_tile64(uint32_t dst, const __half* src, int tid) {
    int row = tid >> 2, q = tid & 3;
    cp16(dst + (uint32_t)row * ROWB + q * 16, src + (size_t)row * 1024 + q * 8);
}

DEVI void split4(float4 v, uint2& hh, uint2& ll) {
    __half h0 = __float2half_rn(v.x), h1 = __float2half_rn(v.y);
    __half h2 = __float2half_rn(v.z), h3 = __float2half_rn(v.w);
    __half l0 = __float2half_rn(v.x - __half2float(h0));
    __half l1 = __float2half_rn(v.y - __half2float(h1));
    __half l2 = __float2half_rn(v.z - __half2float(h2));
    __half l3 = __float2half_rn(v.w - __half2float(h3));
    hh = make_uint2(pack2(h0, h1), pack2(h2, h3));
    ll = make_uint2(pack2(l0, l1), pack2(l2, l3));
}

// ---------------- fused prep kernel ----------------
constexpr int PREP_Q_END = Bn * Sn;            // 8192
constexpr int PREP_K_END = 2 * Bn * Sn;        // 16384
constexpr int PREP_BLOCKS = PREP_K_END + Bn * (Sn / 32) * (Dn / 32); // 24576

__global__ void __launch_bounds__(256)
prep_kernel(const float* __restrict__ Q, const float* __restrict__ K,
            const float* __restrict__ V, const void* st) {
    int blk = blockIdx.x, tid = threadIdx.x;

    if (blk == 0 && tid == 0) {
        const int* p32 = (const int*)st;
        bool is64 = true;
#pragma unroll
        for (int i = 0; i < 4; i++) {
            int lo = p32[2 * i], hi = p32[2 * i + 1];
            is64 = is64 && (hi == 0) && (lo >= 0) && (lo < 6);
        }
        if (is64) {
            const long long* p64 = (const long long*)st;
#pragma unroll
            for (int i = 0; i < Bn; i++) {
                int s = (int)p64[i];
                g_stage[i] = (s < 0) ? 0 : (s > 5 ? 5 : s);
            }
        } else {
#pragma unroll
            for (int i = 0; i < Bn; i++) {
                int s = p32[i];
                g_stage[i] = (s < 0) ? 0 : (s > 5 ? 5 : s);
            }
        }
    }

    if (blk < PREP_Q_END) {
        size_t base = (size_t)blk * Dn;
        float4 v = reinterpret_cast<const float4*>(Q + base)[tid];
        uint2 hh, ll;
        split4(v, hh, ll);
        reinterpret_cast<uint2*>(g_Qh + base)[tid] = hh;
        reinterpret_cast<uint2*>(g_Ql + base)[tid] = ll;
    } else if (blk < PREP_K_END) {
        __shared__ float red[8];
        int row = blk - PREP_Q_END;
        int lane = tid & 31, w = tid >> 5;
        size_t base = (size_t)row * Dn;
        float4 v = reinterpret_cast<const float4*>(K + base)[tid];
        uint2 hh, ll;
        split4(v, hh, ll);
        reinterpret_cast<uint2*>(g_Kh + base)[tid] = hh;
        reinterpret_cast<uint2*>(g_Kl + base)[tid] = ll;
        float s = v.x + v.y + v.z + v.w;
#pragma unroll
        for (int o = 16; o > 0; o >>= 1) s += __shfl_xor_sync(~0u, s, o);
        if (lane == 0) red[w] = s;
        __syncthreads();
        if (tid == 0) {
            float t = red[0];
#pragma unroll
            for (int i = 1; i < 8; i++) t += red[i];
            g_ksum[row] = t;
        }
    } else {
        __shared__ float tile[32][33];
        int vblk = blk - PREP_K_END;
        int b = vblk >> 10;
        int rem = vblk & 1023;
        int t0 = (rem & 31) * 32, d0 = (rem >> 5) * 32;
        int x = tid & 31, y = tid >> 5;  // 32 x 8
        const float* Vb = V + (size_t)b * Sn * Dn;
#pragma unroll
        for (int j = 0; j < 32; j += 8)
            tile[y + j][x] = Vb[(size_t)(t0 + y + j) * Dn + d0 + x];
        __syncthreads();
        size_t ob = (size_t)b * Dn * Sn;
#pragma unroll
        for (int j = 0; j < 32; j += 8) {
            float v = tile[x][y + j];
            __half h = __float2half_rn(v);
            __half l = __float2half_rn(v - __half2float(h));
            size_t idx = ob + (size_t)(d0 + y + j) * Sn + t0 + x;
            g_Vth[idx] = h;
            g_Vtl[idx] = l;
        }
    }
}

// row softmax over g_L -> fp16 P (shuffle reductions, 2 syncs)
__global__ void __launch_bounds__(256)
softmax_kernel() {
    __shared__ float red[8];
    int row = blockIdx.x, tid = threadIdx.x;
    int lane = tid & 31, w = tid >> 5;
    float4 x = reinterpret_cast<const float4*>(g_L + (size_t)row * Sn)[tid];
    float m = fmaxf(fmaxf(x.x, x.y), fmaxf(x.z, x.w));
#pragma unroll
    for (int o = 16; o > 0; o >>= 1) m = fmaxf(m, __shfl_xor_sync(~0u, m, o));
    if (lane == 0) red[w] = m;
    __syncthreads();
    float M = red[0];
#pragma unroll
    for (int i = 1; i < 8; i++) M = fmaxf(M, red[i]);
    __syncthreads();
    float e0 = __expf(x.x - M), e1 = __expf(x.y - M);
    float e2 = __expf(x.z - M), e3 = __expf(x.w - M);
    float s = e0 + e1 + e2 + e3;
#pragma unroll
    for (int o = 16; o > 0; o >>= 1) s += __shfl_xor_sync(~0u, s, o);
    if (lane == 0) red[w] = s;
    __syncthreads();
    float S = red[0];
#pragma unroll
    for (int i = 1; i < 8; i++) S += red[i];
    float inv = 1.0f / S;
    reinterpret_cast<uint2*>(g_Ph + (size_t)row * Sn)[tid] = make_uint2(
        pack2(__float2half_rn(e0 * inv), __float2half_rn(e1 * inv)),
        pack2(__float2half_rn(e2 * inv), __float2half_rn(e3 * inv)));
}

// ---------------- GEMM1 compute: 3-term split, term-major passes ----------------
// Warp grid 4x2: warp tile 32(m) x 32(n). Term-major: 8 independent MMAs
// between reuses of any accumulator; per-acc term order hh->hl->lh preserved.
DEVI void compute_qk(uint32_t st, int lane, int wm, int wn, float acc[2][4][4]) {
    int rsel = lane & 15;
    int csel = (lane >> 4) << 3;
#pragma unroll
    for (int kk = 0; kk < BK; kk += 16) {
        uint32_t aH[2][4], aL[2][4], bH[4][2], bL[4][2];
        uint32_t coff = (uint32_t)(kk + csel) * 2;
#pragma unroll
        for (int mf = 0; mf < 2; mf++) {
            uint32_t rowa = (uint32_t)(wm + mf * 16 + rsel) * ROWB;
            ldsm4(aH[mf], st + S1_AH + rowa + coff);
            ldsm4(aL[mf], st + S1_AL + rowa + coff);
        }
#pragma unroll
        for (int g = 0; g < 2; g++) {
            uint32_t t[4];
            uint32_t rowb = (uint32_t)(wn + g * 16 + rsel) * ROWB;
            ldsm4(t, st + S1_BH + rowb + coff);
            bH[g * 2][0] = t[0]; bH[g * 2][1] = t[2];
            bH[g * 2 + 1][0] = t[1]; bH[g * 2 + 1][1] = t[3];
            ldsm4(t, st + S1_BL + rowb + coff);
            bL[g * 2][0] = t[0]; bL[g * 2][1] = t[2];
            bL[g * 2 + 1][0] = t[1]; bL[g * 2 + 1][1] = t[3];
        }
        // pass 1: hh
#pragma unroll
        for (int mf = 0; mf < 2; mf++)
#pragma unroll
            for (int nf = 0; nf < 4; nf++)
                mma16816(acc[mf][nf], aH[mf], bH[nf]);
        // pass 2: hl
#pragma unroll
        for (int mf = 0; mf < 2; mf++)
#pragma unroll
            for (int nf = 0; nf < 4; nf++)
                mma16816(acc[mf][nf], aH[mf], bL[nf]);
        // pass 3: lh
#pragma unroll
        for (int mf = 0; mf < 2; mf++)
#pragma unroll
            for (int nf = 0; nf < 4; nf++)
                mma16816(acc[mf][nf], aL[mf], bH[nf]);
    }
}

__global__ void __launch_bounds__(256, 3)
gemm_qk(const __half* __restrict__ Abh, const __half* __restrict__ Abl,
        const __half* __restrict__ Bbh, const __half* __restrict__ Bbl,
        float* __restrict__ Cb, const float* __restrict__ emb) {
    extern __shared__ char smem[];
    uint32_t sb = smem_u32(smem);
    int tid = threadIdx.x, lane = tid & 31, warp = tid >> 5;
    int wm = (warp >> 1) * 32, wn = (warp & 1) * 32;
    int m0 = blockIdx.x * BM, n0 = blockIdx.y * BN, b = blockIdx.z;
    size_t off = (size_t)b * Sn * Sn;

    const __half* Ah = Abh + off + (size_t)m0 * 1024;
    const __half* Al = Abl + off + (size_t)m0 * 1024;
    const __half* Bh = Bbh + off + (size_t)n0 * 1024;
    const __half* Bl = Bbl + off + (size_t)n0 * 1024;

    float* ksm = reinterpret_cast<float*>(smem + KS_OFF);
    if (tid < BN) ksm[tid] = g_ksum[b * Sn + n0 + tid];

    float acc[2][4][4] = {};

    load_tile128(sb + S1_AH, Ah, tid);
    load_tile128(sb + S1_AL, Al, tid);
    load_tile64(sb + S1_BH, Bh, tid);
    load_tile64(sb + S1_BL, Bl, tid);
    CP_COMMIT();

    // single-barrier mainloop: wait -> sync -> issue next -> compute current
    for (int c = 0; c < NIT; c++) {
        CP_WAIT0();
        __syncthreads();
        if (c + 1 < NIT) {
            uint32_t d = sb + ((c + 1) & 1) * STAGE1_B;
            load_tile128(d + S1_AH, Ah + (c + 1) * BK, tid);
            load_tile128(d + S1_AL, Al + (c + 1) * BK, tid);
            load_tile64(d + S1_BH, Bh + (c + 1) * BK, tid);
            load_tile64(d + S1_BL, Bl + (c + 1) * BK, tid);
            CP_COMMIT();
        }
        compute_qk(sb + (c & 1) * STAGE1_B, lane, wm, wn, acc);
    }

    int stg = g_stage[b];
#pragma unroll
    for (int mf = 0; mf < 2; mf++) {
        int r0 = wm + mf * 16 + (lane >> 2);
#pragma unroll
        for (int h = 0; h < 2; h++) {
            int row = r0 + h * 8;
            float cr = emb[(size_t)stg * Dn + m0 + row];
            float* out = Cb + off + (size_t)(m0 + row) * 1024 + n0;
#pragma unroll
            for (int nf = 0; nf < 4; nf++) {
                int col = wn + nf * 8 + (lane & 3) * 2;
                float v0 = acc[mf][nf][h * 2 + 0] + cr * ksm[col];
                float v1 = acc[mf][nf][h * 2 + 1] + cr * ksm[col + 1];
                *reinterpret_cast<float2*>(out + col) = make_float2(v0, v1);
            }
        }
    }
}

// ---------------- GEMM2 compute: 2-term, term-major passes ----------------
DEVI void compute_pv(uint32_t st, int lane, int wm, int wn, float acc[2][4][4]) {
    int rsel = lane & 15;
    int csel = (lane >> 4) << 3;
#pragma unroll
    for (int kk = 0; kk < BK; kk += 16) {
        uint32_t a[2][4], bH[4][2], bL[4][2];
        uint32_t coff = (uint32_t)(kk + csel) * 2;
#pragma unroll
        for (int mf = 0; mf < 2; mf++)
            ldsm4(a[mf], st + S2_A + (uint32_t)(wm + mf * 16 + rsel) * ROWB + coff);
#pragma unroll
        for (int g = 0; g < 2; g++) {
            uint32_t t[4];
            uint32_t rowb = (uint32_t)(wn + g * 16 + rsel) * ROWB;
            ldsm4(t, st + S2_BH + rowb + coff);
            bH[g * 2][0] = t[0]; bH[g * 2][1] = t[2];
            bH[g * 2 + 1][0] = t[1]; bH[g * 2 + 1][1] = t[3];
            ldsm4(t, st + S2_BL + rowb + coff);
            bL[g * 2][0] = t[0]; bL[g * 2][1] = t[2];
            bL[g * 2 + 1][0] = t[1]; bL[g * 2 + 1][1] = t[3];
        }
        // pass 1: Ph*Vh
#pragma unroll
        for (int mf = 0; mf < 2; mf++)
#pragma unroll
            for (int nf = 0; nf < 4; nf++)
                mma16816(acc[mf][nf], a[mf], bH[nf]);
        // pass 2: Ph*Vl
#pragma unroll
        for (int mf = 0; mf < 2; mf++)
#pragma unroll
            for (int nf = 0; nf < 4; nf++)
                mma16816(acc[mf][nf], a[mf], bL[nf]);
    }
}

__global__ void __launch_bounds__(256, 4)
gemm_pv(const __half* __restrict__ Pb, const __half* __restrict__ Vbh,
        const __half* __restrict__ Vbl, float* __restrict__ Cb) {
    extern __shared__ char smem[];
    uint32_t sb = smem_u32(smem);
    int tid = threadIdx.x, lane = tid & 31, warp = tid >> 5;
    int wm = (warp >> 1) * 32, wn = (warp & 1) * 32;
    int m0 = blockIdx.x * BM, n0 = blockIdx.y * BN, b = blockIdx.z;

    const __half* A  = Pb  + (size_t)b * Sn * Sn + (size_t)m0 * 1024;
    const __half* Bh = Vbh + (size_t)b * Dn * Sn + (size_t)n0 * 1024;
    const __half* Bl = Vbl + (size_t)b * Dn * Sn + (size_t)n0 * 1024;

    float acc[2][4][4] = {};

    load_tile128(sb + S2_A, A, tid);
    load_tile64(sb + S2_BH, Bh, tid);
    load_tile64(sb + S2_BL, Bl, tid);
    CP_COMMIT();

    for (int c = 0; c < NIT; c++) {
        CP_WAIT0();
        __syncthreads();
        if (c + 1 < NIT) {
            uint32_t d = sb + ((c + 1) & 1) * STAGE2_B;
            load_tile128(d + S2_A, A + (c + 1) * BK, tid);
            load_tile64(d + S2_BH, Bh + (c + 1) * BK, tid);
            load_tile64(d + S2_BL, Bl + (c + 1) * BK, tid);
            CP_COMMIT();
        }
        compute_pv(sb + (c & 1) * STAGE2_B, lane, wm, wn, acc);
    }

#pragma unroll
    for (int mf = 0; mf < 2; mf++) {
        int r0 = wm + mf * 16 + (lane >> 2);
#pragma unroll
        for (int h = 0; h < 2; h++) {
            int row = r0 + h * 8;
            float* out = Cb + (size_t)b * Sn * Dn + (size_t)(m0 + row) * 1024 + n0;
#pragma unroll
            for (int nf = 0; nf < 4; nf++) {
                int col = wn + nf * 8 + (lane & 3) * 2;
                *reinterpret_cast<float2*>(out + col) =
                    make_float2(acc[mf][nf][h * 2 + 0], acc[mf][nf][h * 2 + 1]);
            }
        }
    }
}

// ---------------- launch ----------------
extern "C" void kernel_launch(void* const* d_in, const int* in_sizes, int n_in,
                              void* d_out, int out_size) {
    const float* q   = (const float*)d_in[0];
    const float* k   = (const float*)d_in[1];
    const float* v   = (const float*)d_in[2];
    const float* emb = (const float*)d_in[3];
    const void*  st  = d_in[4];
    float* out = (float*)d_out;

    cudaFuncSetAttribute(gemm_qk, cudaFuncAttributeMaxDynamicSharedMemorySize, SMEM1);
    cudaFuncSetAttribute(gemm_pv, cudaFuncAttributeMaxDynamicSharedMemorySize, SMEM2);

    __half *qh, *ql, *kh, *kl, *vth, *vtl, *ph;
    cudaGetSymbolAddress((void**)&qh,  g_Qh);
    cudaGetSymbolAddress((void**)&ql,  g_Ql);
    cudaGetSymbolAddress((void**)&kh,  g_Kh);
    cudaGetSymbolAddress((void**)&kl,  g_Kl);
    cudaGetSymbolAddress((void**)&vth, g_Vth);
    cudaGetSymbolAddress((void**)&vtl, g_Vtl);
    cudaGetSymbolAddress((void**)&ph,  g_Ph);
    float* gl;
    cudaGetSymbolAddress((void**)&gl, g_L);

    prep_kernel<<<PREP_BLOCKS, 256>>>(q, k, v, st);
    gemm_qk<<<dim3(Sn / BM, Sn / BN, Bn), 256, SMEM1>>>(qh, ql, kh, kl, gl, emb);
    softmax_kernel<<<Bn * Sn, 256>>>();
    gemm_pv<<<dim3(Sn / BM, Dn / BN, Bn), 256, SMEM2>>>(ph, vth, vtl, out);
}

// round 16
// speedup vs baseline: 1.0479x; 1.0479x over previous
#include <cuda_runtime.h>
#include <cuda_fp16.h>
#include <cstdint>
#include <cstddef>

#define DEVI __device__ __forceinline__

// ---------------- problem constants ----------------
constexpr int Bn = 8;
constexpr int Sn = 1024;
constexpr int Dn = 1024;

// ---------------- GEMM tiling ----------------
// BK=64 (best known). pv uses a 3-stage cp.async pipeline (deeper latency
// hiding); qk stays 2-stage (3 stages would drop it to 1 CTA/SM).
constexpr int BM = 128, BN = 64, BK = 64;
constexpr int NIT = Dn / BK;            // 16 k-iterations
constexpr int ROWB = 144;               // padded smem row: 64 halves (128B) + 16B pad
constexpr int TILE_A = BM * ROWB;       // 18432 B (128-row tile)
constexpr int TILE_Bt = BN * ROWB;      // 9216 B  (64-row tile)

// GEMM1 (Q K^T): Ah, Al (128-row) + Bh, Bl (64-row), 2 stages
constexpr int S1_AH = 0, S1_AL = TILE_A, S1_BH = 2 * TILE_A, S1_BL = 2 * TILE_A + TILE_Bt;
constexpr int STAGE1_B = 2 * TILE_A + 2 * TILE_Bt;   // 55296
constexpr int KS_OFF = 2 * STAGE1_B;
constexpr int SMEM1 = KS_OFF + 512;                  // 111104 (2 CTAs/SM)

// GEMM2 (P V): Ph (128-row) + Vh, Vl (64-row), 3 stages
constexpr int S2_A = 0, S2_BH = TILE_A, S2_BL = TILE_A + TILE_Bt;
constexpr int STAGE2_B = TILE_A + 2 * TILE_Bt;       // 36864
constexpr int SMEM2 = 3 * STAGE2_B;                  // 110592 (2 CTAs/SM)

// ---------------- scratch (device globals; no allocation) ----------------
__device__ __half g_Qh[(size_t)Bn * Sn * Dn], g_Ql[(size_t)Bn * Sn * Dn];
__device__ __half g_Kh[(size_t)Bn * Sn * Dn], g_Kl[(size_t)Bn * Sn * Dn];
__device__ __half g_Vth[(size_t)Bn * Dn * Sn], g_Vtl[(size_t)Bn * Dn * Sn]; // V^T [b][d][t]
__device__ __half g_Ph[(size_t)Bn * Sn * Sn];
__device__ float  g_L[(size_t)Bn * Sn * Sn];
__device__ float  g_ksum[Bn * Sn];
__device__ int    g_stage[Bn];

// ---------------- helpers ----------------
DEVI uint32_t smem_u32(const void* p) {
    uint32_t a;
    asm("{ .reg .u64 t; cvta.to.shared.u64 t, %1; cvt.u32.u64 %0, t; }"
        : "=r"(a) : "l"(p));
    return a;
}
DEVI uint32_t pack2(__half a, __half b) {
    __half2 t = __halves2half2(a, b);
    return *reinterpret_cast<uint32_t*>(&t);
}

#define CP_COMMIT() asm volatile("cp.async.commit_group;")
#define CP_WAIT0()  asm volatile("cp.async.wait_group 0;")
#define CP_WAIT1()  asm volatile("cp.async.wait_group 1;")

DEVI void cp16(uint32_t dst, const void* src) {
    asm volatile("cp.async.cg.shared.global [%0], [%1], 16;" :: "r"(dst), "l"(src));
}

DEVI void ldsm4(uint32_t* r, uint32_t addr) {
    asm volatile("ldmatrix.sync.aligned.m8n8.x4.shared.b16 {%0,%1,%2,%3}, [%4];"
        : "=r"(r[0]), "=r"(r[1]), "=r"(r[2]), "=r"(r[3]) : "r"(addr));
}

DEVI void mma16816(float* c, const uint32_t* a, const uint32_t* b) {
    asm volatile(
        "mma.sync.aligned.m16n8k16.row.col.f32.f16.f16.f32 "
        "{%0,%1,%2,%3}, {%4,%5,%6,%7}, {%8,%9}, {%0,%1,%2,%3};"
        : "+f"(c[0]), "+f"(c[1]), "+f"(c[2]), "+f"(c[3])
        : "r"(a[0]), "r"(a[1]), "r"(a[2]), "r"(a[3]), "r"(b[0]), "r"(b[1]));
}

// 128-row x 64-half tile global->smem (1024 x 16B chunks, 4 per thread)
DEVI void load_tile128(uint32_t dst, const __half* src, int tid) {
#pragma unroll
    for (int j = 0; j < 4; j++) {
        int idx = j * 256 + tid;
        int row = idx >> 3, q = idx & 7;
        cp16(dst + (uint32_t)row * ROWB + q * 16, src + (size_t)row * 1024 + q * 8);
    }
}
// 64-row x 64-half tile global->smem (512 x 16B chunks, 2 per thread)
DEVI void load_tile64(uint32_t dst, const __half* src, int tid) {
#pragma unroll
    for (int j = 0; j < 2; j++) {
        int idx = j * 256 + tid;
        int row = idx >> 3, q = idx & 7;
        cp16(dst + (uint32_t)row * ROWB + q * 16, src + (size_t)row * 1024 + q * 8);
    }
}

DEVI void split4(float4 v, uint2& hh, uint2& ll) {
    __half h0 = __float2half_rn(v.x), h1 = __float2half_rn(v.y);
    __half h2 = __float2half_rn(v.z), h3 = __float2half_rn(v.w);
    __half l0 = __float2half_rn(v.x - __half2float(h0));
    __half l1 = __float2half_rn(v.y - __half2float(h1));
    __half l2 = __float2half_rn(v.z - __half2float(h2));
    __half l3 = __float2half_rn(v.w - __half2float(h3));
    hh = make_uint2(pack2(h0, h1), pack2(h2, h3));
    ll = make_uint2(pack2(l0, l1), pack2(l2, l3));
}

// ---------------- fused prep kernel ----------------
constexpr int PREP_Q_END = Bn * Sn;            // 8192
constexpr int PREP_K_END = 2 * Bn * Sn;        // 16384
constexpr int PREP_BLOCKS = PREP_K_END + Bn * (Sn / 32) * (Dn / 32); // 24576

__global__ void __launch_bounds__(256)
prep_kernel(const float* __restrict__ Q, const float* __restrict__ K,
            const float* __restrict__ V, const void* st) {
    int blk = blockIdx.x, tid = threadIdx.x;

    if (blk == 0 && tid == 0) {
        const int* p32 = (const int*)st;
        bool is64 = true;
#pragma unroll
        for (int i = 0; i < 4; i++) {
            int lo = p32[2 * i], hi = p32[2 * i + 1];
            is64 = is64 && (hi == 0) && (lo >= 0) && (lo < 6);
        }
        if (is64) {
            const long long* p64 = (const long long*)st;
#pragma unroll
            for (int i = 0; i < Bn; i++) {
                int s = (int)p64[i];
                g_stage[i] = (s < 0) ? 0 : (s > 5 ? 5 : s);
            }
        } else {
#pragma unroll
            for (int i = 0; i < Bn; i++) {
                int s = p32[i];
                g_stage[i] = (s < 0) ? 0 : (s > 5 ? 5 : s);
            }
        }
    }

    if (blk < PREP_Q_END) {
        size_t base = (size_t)blk * Dn;
        float4 v = reinterpret_cast<const float4*>(Q + base)[tid];
        uint2 hh, ll;
        split4(v, hh, ll);
        reinterpret_cast<uint2*>(g_Qh + base)[tid] = hh;
        reinterpret_cast<uint2*>(g_Ql + base)[tid] = ll;
    } else if (blk < PREP_K_END) {
        __shared__ float red[8];
        int row = blk - PREP_Q_END;
        int lane = tid & 31, w = tid >> 5;
        size_t base = (size_t)row * Dn;
        float4 v = reinterpret_cast<const float4*>(K + base)[tid];
        uint2 hh, ll;
        split4(v, hh, ll);
        reinterpret_cast<uint2*>(g_Kh + base)[tid] = hh;
        reinterpret_cast<uint2*>(g_Kl + base)[tid] = ll;
        float s = v.x + v.y + v.z + v.w;
#pragma unroll
        for (int o = 16; o > 0; o >>= 1) s += __shfl_xor_sync(~0u, s, o);
        if (lane == 0) red[w] = s;
        __syncthreads();
        if (tid == 0) {
            float t = red[0];
#pragma unroll
            for (int i = 1; i < 8; i++) t += red[i];
            g_ksum[row] = t;
        }
    } else {
        __shared__ float tile[32][33];
        int vblk = blk - PREP_K_END;
        int b = vblk >> 10;
        int rem = vblk & 1023;
        int t0 = (rem & 31) * 32, d0 = (rem >> 5) * 32;
        int x = tid & 31, y = tid >> 5;  // 32 x 8
        const float* Vb = V + (size_t)b * Sn * Dn;
#pragma unroll
        for (int j = 0; j < 32; j += 8)
            tile[y + j][x] = Vb[(size_t)(t0 + y + j) * Dn + d0 + x];
        __syncthreads();
        size_t ob = (size_t)b * Dn * Sn;
#pragma unroll
        for (int j = 0; j < 32; j += 8) {
            float v = tile[x][y + j];
            __half h = __float2half_rn(v);
            __half l = __float2half_rn(v - __half2float(h));
            size_t idx = ob + (size_t)(d0 + y + j) * Sn + t0 + x;
            g_Vth[idx] = h;
            g_Vtl[idx] = l;
        }
    }
}

// row softmax over g_L -> fp16 P (shuffle reductions, 2 syncs)
__global__ void __launch_bounds__(256)
softmax_kernel() {
    __shared__ float red[8];
    int row = blockIdx.x, tid = threadIdx.x;
    int lane = tid & 31, w = tid >> 5;
    float4 x = reinterpret_cast<const float4*>(g_L + (size_t)row * Sn)[tid];
    float m = fmaxf(fmaxf(x.x, x.y), fmaxf(x.z, x.w));
#pragma unroll
    for (int o = 16; o > 0; o >>= 1) m = fmaxf(m, __shfl_xor_sync(~0u, m, o));
    if (lane == 0) red[w] = m;
    __syncthreads();
    float M = red[0];
#pragma unroll
    for (int i = 1; i < 8; i++) M = fmaxf(M, red[i]);
    __syncthreads();
    float e0 = __expf(x.x - M), e1 = __expf(x.y - M);
    float e2 = __expf(x.z - M), e3 = __expf(x.w - M);
    float s = e0 + e1 + e2 + e3;
#pragma unroll
    for (int o = 16; o > 0; o >>= 1) s += __shfl_xor_sync(~0u, s, o);
    if (lane == 0) red[w] = s;
    __syncthreads();
    float S = red[0];
#pragma unroll
    for (int i = 1; i < 8; i++) S += red[i];
    float inv = 1.0f / S;
    reinterpret_cast<uint2*>(g_Ph + (size_t)row * Sn)[tid] = make_uint2(
        pack2(__float2half_rn(e0 * inv), __float2half_rn(e1 * inv)),
        pack2(__float2half_rn(e2 * inv), __float2half_rn(e3 * inv)));
}

// ---------------- GEMM1 compute: 3-term split (interleaved order) ----------------
DEVI void compute_qk(uint32_t st, int lane, int wm, int wn, float acc[2][4][4]) {
    int rsel = lane & 15;
    int csel = (lane >> 4) << 3;
#pragma unroll
    for (int kk = 0; kk < BK; kk += 16) {
        uint32_t aH[2][4], aL[2][4], bH[4][2], bL[4][2];
        uint32_t coff = (uint32_t)(kk + csel) * 2;
#pragma unroll
        for (int mf = 0; mf < 2; mf++) {
            uint32_t rowa = (uint32_t)(wm + mf * 16 + rsel) * ROWB;
            ldsm4(aH[mf], st + S1_AH + rowa + coff);
            ldsm4(aL[mf], st + S1_AL + rowa + coff);
        }
#pragma unroll
        for (int g = 0; g < 2; g++) {
            uint32_t t[4];
            uint32_t rowb = (uint32_t)(wn + g * 16 + rsel) * ROWB;
            ldsm4(t, st + S1_BH + rowb + coff);
            bH[g * 2][0] = t[0]; bH[g * 2][1] = t[2];
            bH[g * 2 + 1][0] = t[1]; bH[g * 2 + 1][1] = t[3];
            ldsm4(t, st + S1_BL + rowb + coff);
            bL[g * 2][0] = t[0]; bL[g * 2][1] = t[2];
            bL[g * 2 + 1][0] = t[1]; bL[g * 2 + 1][1] = t[3];
        }
#pragma unroll
        for (int mf = 0; mf < 2; mf++)
#pragma unroll
            for (int nf = 0; nf < 4; nf++) {
                mma16816(acc[mf][nf], aH[mf], bH[nf]);
                mma16816(acc[mf][nf], aH[mf], bL[nf]);
                mma16816(acc[mf][nf], aL[mf], bH[nf]);
            }
    }
}

__global__ void __launch_bounds__(256)
gemm_qk(const __half* __restrict__ Abh, const __half* __restrict__ Abl,
        const __half* __restrict__ Bbh, const __half* __restrict__ Bbl,
        float* __restrict__ Cb, const float* __restrict__ emb) {
    extern __shared__ char smem[];
    uint32_t sb = smem_u32(smem);
    int tid = threadIdx.x, lane = tid & 31, warp = tid >> 5;
    int wm = (warp >> 1) * 32, wn = (warp & 1) * 32;
    int m0 = blockIdx.x * BM, n0 = blockIdx.y * BN, b = blockIdx.z;
    size_t off = (size_t)b * Sn * Sn;

    const __half* Ah = Abh + off + (size_t)m0 * 1024;
    const __half* Al = Abl + off + (size_t)m0 * 1024;
    const __half* Bh = Bbh + off + (size_t)n0 * 1024;
    const __half* Bl = Bbl + off + (size_t)n0 * 1024;

    float* ksm = reinterpret_cast<float*>(smem + KS_OFF);
    if (tid < BN) ksm[tid] = g_ksum[b * Sn + n0 + tid];

    float acc[2][4][4] = {};

    load_tile128(sb + S1_AH, Ah, tid);
    load_tile128(sb + S1_AL, Al, tid);
    load_tile64(sb + S1_BH, Bh, tid);
    load_tile64(sb + S1_BL, Bl, tid);
    CP_COMMIT();

    // 2-stage single-barrier mainloop
    for (int c = 0; c < NIT; c++) {
        CP_WAIT0();
        __syncthreads();
        if (c + 1 < NIT) {
            uint32_t d = sb + ((c + 1) & 1) * STAGE1_B;
            load_tile128(d + S1_AH, Ah + (c + 1) * BK, tid);
            load_tile128(d + S1_AL, Al + (c + 1) * BK, tid);
            load_tile64(d + S1_BH, Bh + (c + 1) * BK, tid);
            load_tile64(d + S1_BL, Bl + (c + 1) * BK, tid);
            CP_COMMIT();
        }
        compute_qk(sb + (c & 1) * STAGE1_B, lane, wm, wn, acc);
    }

    int stg = g_stage[b];
#pragma unroll
    for (int mf = 0; mf < 2; mf++) {
        int r0 = wm + mf * 16 + (lane >> 2);
#pragma unroll
        for (int h = 0; h < 2; h++) {
            int row = r0 + h * 8;
            float cr = emb[(size_t)stg * Dn + m0 + row];
            float* out = Cb + off + (size_t)(m0 + row) * 1024 + n0;
#pragma unroll
            for (int nf = 0; nf < 4; nf++) {
                int col = wn + nf * 8 + (lane & 3) * 2;
                float v0 = acc[mf][nf][h * 2 + 0] + cr * ksm[col];
                float v1 = acc[mf][nf][h * 2 + 1] + cr * ksm[col + 1];
                *reinterpret_cast<float2*>(out + col) = make_float2(v0, v1);
            }
        }
    }
}

// ---------------- GEMM2 compute: 2-term (Ph*Vh + Ph*Vl) ----------------
DEVI void compute_pv(uint32_t st, int lane, int wm, int wn, float acc[2][4][4]) {
    int rsel = lane & 15;
    int csel = (lane >> 4) << 3;
#pragma unroll
    for (int kk = 0; kk < BK; kk += 16) {
        uint32_t a[2][4], bH[4][2], bL[4][2];
        uint32_t coff = (uint32_t)(kk + csel) * 2;
#pragma unroll
        for (int mf = 0; mf < 2; mf++)
            ldsm4(a[mf], st + S2_A + (uint32_t)(wm + mf * 16 + rsel) * ROWB + coff);
#pragma unroll
        for (int g = 0; g < 2; g++) {
            uint32_t t[4];
            uint32_t rowb = (uint32_t)(wn + g * 16 + rsel) * ROWB;
            ldsm4(t, st + S2_BH + rowb + coff);
            bH[g * 2][0] = t[0]; bH[g * 2][1] = t[2];
            bH[g * 2 + 1][0] = t[1]; bH[g * 2 + 1][1] = t[3];
            ldsm4(t, st + S2_BL + rowb + coff);
            bL[g * 2][0] = t[0]; bL[g * 2][1] = t[2];
            bL[g * 2 + 1][0] = t[1]; bL[g * 2 + 1][1] = t[3];
        }
#pragma unroll
        for (int mf = 0; mf < 2; mf++)
#pragma unroll
            for (int nf = 0; nf < 4; nf++) {
                mma16816(acc[mf][nf], a[mf], bH[nf]);
                mma16816(acc[mf][nf], a[mf], bL[nf]);
            }
    }
}

DEVI void pv_issue(uint32_t sb, const __half* A, const __half* Bh,
                   const __half* Bl, int c, int tid) {
    uint32_t d = sb + (uint32_t)(c % 3) * STAGE2_B;
    load_tile128(d + S2_A, A + c * BK, tid);
    load_tile64(d + S2_BH, Bh + c * BK, tid);
    load_tile64(d + S2_BL, Bl + c * BK, tid);
    CP_COMMIT();
}

__global__ void __launch_bounds__(256)
gemm_pv(const __half* __restrict__ Pb, const __half* __restrict__ Vbh,
        const __half* __restrict__ Vbl, float* __restrict__ Cb) {
    extern __shared__ char smem[];
    uint32_t sb = smem_u32(smem);
    int tid = threadIdx.x, lane = tid & 31, warp = tid >> 5;
    int wm = (warp >> 1) * 32, wn = (warp & 1) * 32;
    int m0 = blockIdx.x * BM, n0 = blockIdx.y * BN, b = blockIdx.z;

    const __half* A  = Pb  + (size_t)b * Sn * Sn + (size_t)m0 * 1024;
    const __half* Bh = Vbh + (size_t)b * Dn * Sn + (size_t)n0 * 1024;
    const __half* Bl = Vbl + (size_t)b * Dn * Sn + (size_t)n0 * 1024;

    float acc[2][4][4] = {};

    // 3-stage prologue: chunks 0 and 1 in flight
    pv_issue(sb, A, Bh, Bl, 0, tid);
    pv_issue(sb, A, Bh, Bl, 1, tid);

    // 3-stage mainloop: wait(chunk c done, c+1 may fly) -> sync -> issue c+2
    // -> compute c. Tail: last iteration has only group c pending => wait0.
    for (int c = 0; c < NIT; c++) {
        if (c + 1 < NIT) CP_WAIT1(); else CP_WAIT0();
        __syncthreads();
        if (c + 2 < NIT) pv_issue(sb, A, Bh, Bl, c + 2, tid);
        compute_pv(sb + (uint32_t)(c % 3) * STAGE2_B, lane, wm, wn, acc);
    }

#pragma unroll
    for (int mf = 0; mf < 2; mf++) {
        int r0 = wm + mf * 16 + (lane >> 2);
#pragma unroll
        for (int h = 0; h < 2; h++) {
            int row = r0 + h * 8;
            float* out = Cb + (size_t)b * Sn * Dn + (size_t)(m0 + row) * 1024 + n0;
#pragma unroll
            for (int nf = 0; nf < 4; nf++) {
                int col = wn + nf * 8 + (lane & 3) * 2;
                *reinterpret_cast<float2*>(out + col) =
                    make_float2(acc[mf][nf][h * 2 + 0], acc[mf][nf][h * 2 + 1]);
            }
        }
    }
}

// ---------------- launch ----------------
extern "C" void kernel_launch(void* const* d_in, const int* in_sizes, int n_in,
                              void* d_out, int out_size) {
    const float* q   = (const float*)d_in[0];
    const float* k   = (const float*)d_in[1];
    const float* v   = (const float*)d_in[2];
    const float* emb = (const float*)d_in[3];
    const void*  st  = d_in[4];
    float* out = (float*)d_out;

    cudaFuncSetAttribute(gemm_qk, cudaFuncAttributeMaxDynamicSharedMemorySize, SMEM1);
    cudaFuncSetAttribute(gemm_pv, cudaFuncAttributeMaxDynamicSharedMemorySize, SMEM2);

    __half *qh, *ql, *kh, *kl, *vth, *vtl, *ph;
    cudaGetSymbolAddress((void**)&qh,  g_Qh);
    cudaGetSymbolAddress((void**)&ql,  g_Ql);
    cudaGetSymbolAddress((void**)&kh,  g_Kh);
    cudaGetSymbolAddress((void**)&kl,  g_Kl);
    cudaGetSymbolAddress((void**)&vth, g_Vth);
    cudaGetSymbolAddress((void**)&vtl, g_Vtl);
    cudaGetSymbolAddress((void**)&ph,  g_Ph);
    float* gl;
    cudaGetSymbolAddress((void**)&gl, g_L);

    prep_kernel<<<PREP_BLOCKS, 256>>>(q, k, v, st);
    gemm_qk<<<dim3(Sn / BM, Sn / BN, Bn), 256, SMEM1>>>(qh, ql, kh, kl, gl, emb);
    softmax_kernel<<<Bn * Sn, 256>>>();
    gemm_pv<<<dim3(Sn / BM, Dn / BN, Bn), 256, SMEM2>>>(ph, vth, vtl, out);
}

// round 17
// speedup vs baseline: 1.0749x; 1.0258x over previous
#include <cuda_runtime.h>
#include <cuda_fp16.h>
#include <cstdint>
#include <cstddef>

#define DEVI __device__ __forceinline__

// ---------------- problem constants ----------------
constexpr int Bn = 8;
constexpr int Sn = 1024;
constexpr int Dn = 1024;

// ---------------- GEMM tiling (R13 best config + persistent scheduling) ----
constexpr int BM = 128, BN = 64, BK = 64;
constexpr int NIT = Dn / BK;            // 16 k-iterations
constexpr int ROWB = 144;               // padded smem row: 64 halves (128B) + 16B pad
constexpr int TILE_A = BM * ROWB;       // 18432 B (128-row tile)
constexpr int TILE_Bt = BN * ROWB;      // 9216 B  (64-row tile)
constexpr int NTILES = (Sn / BM) * (Sn / BN) * Bn;   // 1024 tiles per GEMM

// GEMM1 (Q K^T): Ah, Al (128-row) + Bh, Bl (64-row), 2 stages
constexpr int S1_AH = 0, S1_AL = TILE_A, S1_BH = 2 * TILE_A, S1_BL = 2 * TILE_A + TILE_Bt;
constexpr int STAGE1_B = 2 * TILE_A + 2 * TILE_Bt;   // 55296
constexpr int KS_OFF = 2 * STAGE1_B;
constexpr int SMEM1 = KS_OFF + 512;                  // 111104 (2 CTAs/SM)

// GEMM2 (P V): Ph (128-row) + Vh, Vl (64-row), 2 stages
constexpr int S2_A = 0, S2_BH = TILE_A, S2_BL = TILE_A + TILE_Bt;
constexpr int STAGE2_B = TILE_A + 2 * TILE_Bt;       // 36864
constexpr int SMEM2 = 2 * STAGE2_B;                  // 73728 (3 CTAs/SM)

// ---------------- scratch (device globals; no allocation) ----------------
__device__ __half g_Qh[(size_t)Bn * Sn * Dn], g_Ql[(size_t)Bn * Sn * Dn];
__device__ __half g_Kh[(size_t)Bn * Sn * Dn], g_Kl[(size_t)Bn * Sn * Dn];
__device__ __half g_Vth[(size_t)Bn * Dn * Sn], g_Vtl[(size_t)Bn * Dn * Sn]; // V^T [b][d][t]
__device__ __half g_Ph[(size_t)Bn * Sn * Sn];
__device__ float  g_L[(size_t)Bn * Sn * Sn];
__device__ float  g_ksum[Bn * Sn];
__device__ int    g_stage[Bn];
__device__ int    g_ctr[2];             // persistent tile counters (qk, pv)

// ---------------- helpers ----------------
DEVI uint32_t smem_u32(const void* p) {
    uint32_t a;
    asm("{ .reg .u64 t; cvta.to.shared.u64 t, %1; cvt.u32.u64 %0, t; }"
        : "=r"(a) : "l"(p));
    return a;
}
DEVI uint32_t pack2(__half a, __half b) {
    __half2 t = __halves2half2(a, b);
    return *reinterpret_cast<uint32_t*>(&t);
}

#define CP_COMMIT() asm volatile("cp.async.commit_group;")
#define CP_WAIT0()  asm volatile("cp.async.wait_group 0;")

DEVI void cp16(uint32_t dst, const void* src) {
    asm volatile("cp.async.cg.shared.global [%0], [%1], 16;" :: "r"(dst), "l"(src));
}

DEVI void ldsm4(uint32_t* r, uint32_t addr) {
    asm volatile("ldmatrix.sync.aligned.m8n8.x4.shared.b16 {%0,%1,%2,%3}, [%4];"
        : "=r"(r[0]), "=r"(r[1]), "=r"(r[2]), "=r"(r[3]) : "r"(addr));
}

DEVI void mma16816(float* c, const uint32_t* a, const uint32_t* b) {
    asm volatile(
        "mma.sync.aligned.m16n8k16.row.col.f32.f16.f16.f32 "
        "{%0,%1,%2,%3}, {%4,%5,%6,%7}, {%8,%9}, {%0,%1,%2,%3};"
        : "+f"(c[0]), "+f"(c[1]), "+f"(c[2]), "+f"(c[3])
        : "r"(a[0]), "r"(a[1]), "r"(a[2]), "r"(a[3]), "r"(b[0]), "r"(b[1]));
}

// 128-row x 64-half tile global->smem (1024 x 16B chunks, 4 per thread)
DEVI void load_tile128(uint32_t dst, const __half* src, int tid) {
#pragma unroll
    for (int j = 0; j < 4; j++) {
        int idx = j * 256 + tid;
        int row = idx >> 3, q = idx & 7;
        cp16(dst + (uint32_t)row * ROWB + q * 16, src + (size_t)row * 1024 + q * 8);
    }
}
// 64-row x 64-half tile global->smem (512 x 16B chunks, 2 per thread)
DEVI void load_tile64(uint32_t dst, const __half* src, int tid) {
#pragma unroll
    for (int j = 0; j < 2; j++) {
        int idx = j * 256 + tid;
        int row = idx >> 3, q = idx & 7;
        cp16(dst + (uint32_t)row * ROWB + q * 16, src + (size_t)row * 1024 + q * 8);
    }
}

DEVI void split4(float4 v, uint2& hh, uint2& ll) {
    __half h0 = __float2half_rn(v.x), h1 = __float2half_rn(v.y);
    __half h2 = __float2half_rn(v.z), h3 = __float2half_rn(v.w);
    __half l0 = __float2half_rn(v.x - __half2float(h0));
    __half l1 = __float2half_rn(v.y - __half2float(h1));
    __half l2 = __float2half_rn(v.z - __half2float(h2));
    __half l3 = __float2half_rn(v.w - __half2float(h3));
    hh = make_uint2(pack2(h0, h1), pack2(h2, h3));
    ll = make_uint2(pack2(l0, l1), pack2(l2, l3));
}

// ---------------- fused prep kernel ----------------
constexpr int PREP_Q_END = Bn * Sn;            // 8192
constexpr int PREP_K_END = 2 * Bn * Sn;        // 16384
constexpr int PREP_BLOCKS = PREP_K_END + Bn * (Sn / 32) * (Dn / 32); // 24576

__global__ void __launch_bounds__(256)
prep_kernel(const float* __restrict__ Q, const float* __restrict__ K,
            const float* __restrict__ V, const void* st) {
    int blk = blockIdx.x, tid = threadIdx.x;

    if (blk == 0 && tid == 0) {
        g_ctr[0] = 0;
        g_ctr[1] = 0;
        const int* p32 = (const int*)st;
        bool is64 = true;
#pragma unroll
        for (int i = 0; i < 4; i++) {
            int lo = p32[2 * i], hi = p32[2 * i + 1];
            is64 = is64 && (hi == 0) && (lo >= 0) && (lo < 6);
        }
        if (is64) {
            const long long* p64 = (const long long*)st;
#pragma unroll
            for (int i = 0; i < Bn; i++) {
                int s = (int)p64[i];
                g_stage[i] = (s < 0) ? 0 : (s > 5 ? 5 : s);
            }
        } else {
#pragma unroll
            for (int i = 0; i < Bn; i++) {
                int s = p32[i];
                g_stage[i] = (s < 0) ? 0 : (s > 5 ? 5 : s);
            }
        }
    }

    if (blk < PREP_Q_END) {
        size_t base = (size_t)blk * Dn;
        float4 v = reinterpret_cast<const float4*>(Q + base)[tid];
        uint2 hh, ll;
        split4(v, hh, ll);
        reinterpret_cast<uint2*>(g_Qh + base)[tid] = hh;
        reinterpret_cast<uint2*>(g_Ql + base)[tid] = ll;
    } else if (blk < PREP_K_END) {
        __shared__ float red[8];
        int row = blk - PREP_Q_END;
        int lane = tid & 31, w = tid >> 5;
        size_t base = (size_t)row * Dn;
        float4 v = reinterpret_cast<const float4*>(K + base)[tid];
        uint2 hh, ll;
        split4(v, hh, ll);
        reinterpret_cast<uint2*>(g_Kh + base)[tid] = hh;
        reinterpret_cast<uint2*>(g_Kl + base)[tid] = ll;
        float s = v.x + v.y + v.z + v.w;
#pragma unroll
        for (int o = 16; o > 0; o >>= 1) s += __shfl_xor_sync(~0u, s, o);
        if (lane == 0) red[w] = s;
        __syncthreads();
        if (tid == 0) {
            float t = red[0];
#pragma unroll
            for (int i = 1; i < 8; i++) t += red[i];
            g_ksum[row] = t;
        }
    } else {
        __shared__ float tile[32][33];
        int vblk = blk - PREP_K_END;
        int b = vblk >> 10;
        int rem = vblk & 1023;
        int t0 = (rem & 31) * 32, d0 = (rem >> 5) * 32;
        int x = tid & 31, y = tid >> 5;  // 32 x 8
        const float* Vb = V + (size_t)b * Sn * Dn;
#pragma unroll
        for (int j = 0; j < 32; j += 8)
            tile[y + j][x] = Vb[(size_t)(t0 + y + j) * Dn + d0 + x];
        __syncthreads();
        size_t ob = (size_t)b * Dn * Sn;
#pragma unroll
        for (int j = 0; j < 32; j += 8) {
            float v = tile[x][y + j];
            __half h = __float2half_rn(v);
            __half l = __float2half_rn(v - __half2float(h));
            size_t idx = ob + (size_t)(d0 + y + j) * Sn + t0 + x;
            g_Vth[idx] = h;
            g_Vtl[idx] = l;
        }
    }
}

// row softmax over g_L -> fp16 P (shuffle reductions, 2 syncs)
__global__ void __launch_bounds__(256)
softmax_kernel() {
    __shared__ float red[8];
    int row = blockIdx.x, tid = threadIdx.x;
    int lane = tid & 31, w = tid >> 5;
    float4 x = reinterpret_cast<const float4*>(g_L + (size_t)row * Sn)[tid];
    float m = fmaxf(fmaxf(x.x, x.y), fmaxf(x.z, x.w));
#pragma unroll
    for (int o = 16; o > 0; o >>= 1) m = fmaxf(m, __shfl_xor_sync(~0u, m, o));
    if (lane == 0) red[w] = m;
    __syncthreads();
    float M = red[0];
#pragma unroll
    for (int i = 1; i < 8; i++) M = fmaxf(M, red[i]);
    __syncthreads();
    float e0 = __expf(x.x - M), e1 = __expf(x.y - M);
    float e2 = __expf(x.z - M), e3 = __expf(x.w - M);
    float s = e0 + e1 + e2 + e3;
#pragma unroll
    for (int o = 16; o > 0; o >>= 1) s += __shfl_xor_sync(~0u, s, o);
    if (lane == 0) red[w] = s;
    __syncthreads();
    float S = red[0];
#pragma unroll
    for (int i = 1; i < 8; i++) S += red[i];
    float inv = 1.0f / S;
    reinterpret_cast<uint2*>(g_Ph + (size_t)row * Sn)[tid] = make_uint2(
        pack2(__float2half_rn(e0 * inv), __float2half_rn(e1 * inv)),
        pack2(__float2half_rn(e2 * inv), __float2half_rn(e3 * inv)));
}

// ---------------- GEMM1 compute: 3-term split (interleaved order) ----------------
DEVI void compute_qk(uint32_t st, int lane, int wm, int wn, float acc[2][4][4]) {
    int rsel = lane & 15;
    int csel = (lane >> 4) << 3;
#pragma unroll
    for (int kk = 0; kk < BK; kk += 16) {
        uint32_t aH[2][4], aL[2][4], bH[4][2], bL[4][2];
        uint32_t coff = (uint32_t)(kk + csel) * 2;
#pragma unroll
        for (int mf = 0; mf < 2; mf++) {
            uint32_t rowa = (uint32_t)(wm + mf * 16 + rsel) * ROWB;
            ldsm4(aH[mf], st + S1_AH + rowa + coff);
            ldsm4(aL[mf], st + S1_AL + rowa + coff);
        }
#pragma unroll
        for (int g = 0; g < 2; g++) {
            uint32_t t[4];
            uint32_t rowb = (uint32_t)(wn + g * 16 + rsel) * ROWB;
            ldsm4(t, st + S1_BH + rowb + coff);
            bH[g * 2][0] = t[0]; bH[g * 2][1] = t[2];
            bH[g * 2 + 1][0] = t[1]; bH[g * 2 + 1][1] = t[3];
            ldsm4(t, st + S1_BL + rowb + coff);
            bL[g * 2][0] = t[0]; bL[g * 2][1] = t[2];
            bL[g * 2 + 1][0] = t[1]; bL[g * 2 + 1][1] = t[3];
        }
#pragma unroll
        for (int mf = 0; mf < 2; mf++)
#pragma unroll
            for (int nf = 0; nf < 4; nf++) {
                mma16816(acc[mf][nf], aH[mf], bH[nf]);
                mma16816(acc[mf][nf], aH[mf], bL[nf]);
                mma16816(acc[mf][nf], aL[mf], bH[nf]);
            }
    }
}

// Persistent: CTAs steal tiles via g_ctr[0]. Tile decode: b = t>>7,
// mi = (t>>4)&7, ni = t&15.
__global__ void __launch_bounds__(256)
gemm_qk(const __half* __restrict__ Abh, const __half* __restrict__ Abl,
        const __half* __restrict__ Bbh, const __half* __restrict__ Bbl,
        float* __restrict__ Cb, const float* __restrict__ emb) {
    extern __shared__ char smem[];
    __shared__ int ts;
    uint32_t sb = smem_u32(smem);
    int tid = threadIdx.x, lane = tid & 31, warp = tid >> 5;
    int wm = (warp >> 1) * 32, wn = (warp & 1) * 32;

    while (true) {
        if (tid == 0) ts = atomicAdd(&g_ctr[0], 1);
        __syncthreads();
        int t = ts;
        if (t >= NTILES) break;
        int b = t >> 7, mi = (t >> 4) & 7, ni = t & 15;
        int m0 = mi * BM, n0 = ni * BN;
        size_t off = (size_t)b * Sn * Sn;

        const __half* Ah = Abh + off + (size_t)m0 * 1024;
        const __half* Al = Abl + off + (size_t)m0 * 1024;
        const __half* Bh = Bbh + off + (size_t)n0 * 1024;
        const __half* Bl = Bbl + off + (size_t)n0 * 1024;

        float* ksm = reinterpret_cast<float*>(smem + KS_OFF);
        if (tid < BN) ksm[tid] = g_ksum[b * Sn + n0 + tid];

        float acc[2][4][4] = {};

        load_tile128(sb + S1_AH, Ah, tid);
        load_tile128(sb + S1_AL, Al, tid);
        load_tile64(sb + S1_BH, Bh, tid);
        load_tile64(sb + S1_BL, Bl, tid);
        CP_COMMIT();

        for (int c = 0; c < NIT; c++) {
            CP_WAIT0();
            __syncthreads();
            if (c + 1 < NIT) {
                uint32_t d = sb + ((c + 1) & 1) * STAGE1_B;
                load_tile128(d + S1_AH, Ah + (c + 1) * BK, tid);
                load_tile128(d + S1_AL, Al + (c + 1) * BK, tid);
                load_tile64(d + S1_BH, Bh + (c + 1) * BK, tid);
                load_tile64(d + S1_BL, Bl + (c + 1) * BK, tid);
                CP_COMMIT();
            }
            compute_qk(sb + (c & 1) * STAGE1_B, lane, wm, wn, acc);
        }

        int stg = g_stage[b];
#pragma unroll
        for (int mf = 0; mf < 2; mf++) {
            int r0 = wm + mf * 16 + (lane >> 2);
#pragma unroll
            for (int h = 0; h < 2; h++) {
                int row = r0 + h * 8;
                float cr = emb[(size_t)stg * Dn + m0 + row];
                float* out = Cb + off + (size_t)(m0 + row) * 1024 + n0;
#pragma unroll
                for (int nf = 0; nf < 4; nf++) {
                    int col = wn + nf * 8 + (lane & 3) * 2;
                    float v0 = acc[mf][nf][h * 2 + 0] + cr * ksm[col];
                    float v1 = acc[mf][nf][h * 2 + 1] + cr * ksm[col + 1];
                    *reinterpret_cast<float2*>(out + col) = make_float2(v0, v1);
                }
            }
        }
    }
}

// ---------------- GEMM2 compute: 2-term (Ph*Vh + Ph*Vl) ----------------
DEVI void compute_pv(uint32_t st, int lane, int wm, int wn, float acc[2][4][4]) {
    int rsel = lane & 15;
    int csel = (lane >> 4) << 3;
#pragma unroll
    for (int kk = 0; kk < BK; kk += 16) {
        uint32_t a[2][4], bH[4][2], bL[4][2];
        uint32_t coff = (uint32_t)(kk + csel) * 2;
#pragma unroll
        for (int mf = 0; mf < 2; mf++)
            ldsm4(a[mf], st + S2_A + (uint32_t)(wm + mf * 16 + rsel) * ROWB + coff);
#pragma unroll
        for (int g = 0; g < 2; g++) {
            uint32_t t[4];
            uint32_t rowb = (uint32_t)(wn + g * 16 + rsel) * ROWB;
            ldsm4(t, st + S2_BH + rowb + coff);
            bH[g * 2][0] = t[0]; bH[g * 2][1] = t[2];
            bH[g * 2 + 1][0] = t[1]; bH[g * 2 + 1][1] = t[3];
            ldsm4(t, st + S2_BL + rowb + coff);
            bL[g * 2][0] = t[0]; bL[g * 2][1] = t[2];
            bL[g * 2 + 1][0] = t[1]; bL[g * 2 + 1][1] = t[3];
        }
#pragma unroll
        for (int mf = 0; mf < 2; mf++)
#pragma unroll
            for (int nf = 0; nf < 4; nf++) {
                mma16816(acc[mf][nf], a[mf], bH[nf]);
                mma16816(acc[mf][nf], a[mf], bL[nf]);
            }
    }
}

// Persistent: CTAs steal tiles via g_ctr[1].
__global__ void __launch_bounds__(256)
gemm_pv(const __half* __restrict__ Pb, const __half* __restrict__ Vbh,
        const __half* __restrict__ Vbl, float* __restrict__ Cb) {
    extern __shared__ char smem[];
    __shared__ int ts;
    uint32_t sb = smem_u32(smem);
    int tid = threadIdx.x, lane = tid & 31, warp = tid >> 5;
    int wm = (warp >> 1) * 32, wn = (warp & 1) * 32;

    while (true) {
        if (tid == 0) ts = atomicAdd(&g_ctr[1], 1);
        __syncthreads();
        int t = ts;
        if (t >= NTILES) break;
        int b = t >> 7, mi = (t >> 4) & 7, ni = t & 15;
        int m0 = mi * BM, n0 = ni * BN;

        const __half* A  = Pb  + (size_t)b * Sn * Sn + (size_t)m0 * 1024;
        const __half* Bh = Vbh + (size_t)b * Dn * Sn + (size_t)n0 * 1024;
        const __half* Bl = Vbl + (size_t)b * Dn * Sn + (size_t)n0 * 1024;

        float acc[2][4][4] = {};

        load_tile128(sb + S2_A, A, tid);
        load_tile64(sb + S2_BH, Bh, tid);
        load_tile64(sb + S2_BL, Bl, tid);
        CP_COMMIT();

        for (int c = 0; c < NIT; c++) {
            CP_WAIT0();
            __syncthreads();
            if (c + 1 < NIT) {
                uint32_t d = sb + ((c + 1) & 1) * STAGE2_B;
                load_tile128(d + S2_A, A + (c + 1) * BK, tid);
                load_tile64(d + S2_BH, Bh + (c + 1) * BK, tid);
                load_tile64(d + S2_BL, Bl + (c + 1) * BK, tid);
                CP_COMMIT();
            }
            compute_pv(sb + (c & 1) * STAGE2_B, lane, wm, wn, acc);
        }

#pragma unroll
        for (int mf = 0; mf < 2; mf++) {
            int r0 = wm + mf * 16 + (lane >> 2);
#pragma unroll
            for (int h = 0; h < 2; h++) {
                int row = r0 + h * 8;
                float* out = Cb + (size_t)b * Sn * Dn + (size_t)(m0 + row) * 1024 + n0;
#pragma unroll
                for (int nf = 0; nf < 4; nf++) {
                    int col = wn + nf * 8 + (lane & 3) * 2;
                    *reinterpret_cast<float2*>(out + col) =
                        make_float2(acc[mf][nf][h * 2 + 0], acc[mf][nf][h * 2 + 1]);
                }
            }
        }
    }
}

// ---------------- launch ----------------
extern "C" void kernel_launch(void* const* d_in, const int* in_sizes, int n_in,
                              void* d_out, int out_size) {
    const float* q   = (const float*)d_in[0];
    const float* k   = (const float*)d_in[1];
    const float* v   = (const float*)d_in[2];
    const float* emb = (const float*)d_in[3];
    const void*  st  = d_in[4];
    float* out = (float*)d_out;

    cudaFuncSetAttribute(gemm_qk, cudaFuncAttributeMaxDynamicSharedMemorySize, SMEM1);
    cudaFuncSetAttribute(gemm_pv, cudaFuncAttributeMaxDynamicSharedMemorySize, SMEM2);

    __half *qh, *ql, *kh, *kl, *vth, *vtl, *ph;
    cudaGetSymbolAddress((void**)&qh,  g_Qh);
    cudaGetSymbolAddress((void**)&ql,  g_Ql);
    cudaGetSymbolAddress((void**)&kh,  g_Kh);
    cudaGetSymbolAddress((void**)&kl,  g_Kl);
    cudaGetSymbolAddress((void**)&vth, g_Vth);
    cudaGetSymbolAddress((void**)&vtl, g_Vtl);
    cudaGetSymbolAddress((void**)&ph,  g_Ph);
    float* gl;
    cudaGetSymbolAddress((void**)&gl, g_L);

    prep_kernel<<<PREP_BLOCKS, 256>>>(q, k, v, st);
    gemm_qk<<<NTILES, 256, SMEM1>>>(qh, ql, kh, kl, gl, emb);
    softmax_kernel<<<Bn * Sn, 256>>>();
    gemm_pv<<<NTILES, 256, SMEM2>>>(ph, vth, vtl, out);
}